// round 1
// baseline (speedup 1.0000x reference)
#include <cuda_runtime.h>
#include <math.h>

#define LEN   4096
#define NFFT  8192
#define NBF   (NFFT/2)
#define NB    4
#define NC    2
#define NH    768
#define CHN   (NC*NH)          // 1536
#define NBINS (NFFT/2 + 1)     // 4097
#define LAM   0.1f

// Scratch (static __device__ arrays per harness rules)
__device__ float2 g_Kf[(size_t)CHN * NBINS];        // ~50 MB
__device__ float2 g_Uf[(size_t)NB * NH * NBINS];    // ~100 MB
__device__ float  g_Yg[(size_t)NB * CHN * LEN];     // ~100 MB

__device__ __forceinline__ float2 cmul(float2 a, float2 b) {
    return make_float2(a.x*b.x - a.y*b.y, a.x*b.y + a.y*b.x);
}

// Stockham radix-2 FFT, n=8192, output in natural order. SIGN=-1 forward, +1 inverse (unnormalized).
// Returns pointer to the buffer holding the result.
template<int SIGN>
__device__ float2* fft8192(float2* X, float2* Y) {
    float2* src = X;
    float2* dst = Y;
    int ls = 0;
    #pragma unroll 1
    for (int len = NFFT; len > 1; len >>= 1) {
        int m = len >> 1;
        float theta = (float)SIGN * 6.283185307179586f / (float)len;
        __syncthreads();
        int s = 1 << ls;
        for (int i = threadIdx.x; i < NBF; i += blockDim.x) {
            int p = i >> ls;
            int q = i & (s - 1);
            float2 a = src[q + (p << ls)];
            float2 b = src[q + ((p + m) << ls)];
            float2 sum = make_float2(a.x + b.x, a.y + b.y);
            float2 dif = make_float2(a.x - b.x, a.y - b.y);
            float sn, cs;
            __sincosf(theta * (float)p, &sn, &cs);
            dst[q + ((2*p)   << ls)] = sum;
            dst[q + ((2*p+1) << ls)] = make_float2(dif.x*cs - dif.y*sn,
                                                   dif.x*sn + dif.y*cs);
        }
        float2* t = src; src = dst; dst = t;
        ls++;
    }
    __syncthreads();
    return src;
}

// Kernel 1: soft-threshold + rFFT of the convolution kernel. grid = C*H
__global__ void __launch_bounds__(1024) kf_kernel(const float* __restrict__ kern) {
    extern __shared__ float2 sm[];
    float2* X = sm;
    float2* Y = sm + NFFT;
    int ch = blockIdx.x;
    const float* kp = kern + (size_t)ch * NFFT;
    for (int i = threadIdx.x; i < NFFT; i += blockDim.x) {
        float x = kp[i];
        float a = fabsf(x) - LAM;
        float v = (a > 0.f) ? copysignf(a, x) : 0.f;
        X[i] = make_float2(v, 0.f);
    }
    float2* R = fft8192<-1>(X, Y);
    float2* dstp = g_Kf + (size_t)ch * NBINS;
    for (int i = threadIdx.x; i < NBINS; i += blockDim.x) dstp[i] = R[i];
}

// Kernel 2: zero-padded rFFT of u. grid = B*H
__global__ void __launch_bounds__(1024) uf_kernel(const float* __restrict__ u) {
    extern __shared__ float2 sm[];
    float2* X = sm;
    float2* Y = sm + NFFT;
    int bh = blockIdx.x;
    const float* up = u + (size_t)bh * LEN;
    for (int i = threadIdx.x; i < NFFT; i += blockDim.x) {
        float v = (i < LEN) ? up[i] : 0.f;
        X[i] = make_float2(v, 0.f);
    }
    float2* R = fft8192<-1>(X, Y);
    float2* dstp = g_Uf + (size_t)bh * NBINS;
    for (int i = threadIdx.x; i < NBINS; i += blockDim.x) dstp[i] = R[i];
}

// Kernel 3: spectral product -> iFFT -> skip + GELU. grid = B*C*H
__global__ void __launch_bounds__(1024) conv_kernel(const float* __restrict__ u,
                                                    const float* __restrict__ Dm) {
    extern __shared__ float2 sm[];
    float2* X = sm;
    float2* Y = sm + NFFT;
    int idx = blockIdx.x;
    int b   = idx / CHN;
    int chn = idx - b * CHN;   // c*H + h
    int h   = chn % NH;
    const float2* Ufp = g_Uf + (size_t)(b * NH + h) * NBINS;
    const float2* Kfp = g_Kf + (size_t)chn * NBINS;
    const float scale = 1.0f / (float)NFFT;   // irfft normalization
    for (int k = threadIdx.x; k < NBINS; k += blockDim.x) {
        float2 p = cmul(Ufp[k], Kfp[k]);
        X[k] = make_float2(p.x * scale, p.y * scale);
    }
    __syncthreads();
    // Hermitian mirror
    for (int k = NBINS + threadIdx.x; k < NFFT; k += blockDim.x) {
        float2 p = X[NFFT - k];
        X[k] = make_float2(p.x, -p.y);
    }
    float2* R = fft8192<1>(X, Y);
    float d = Dm[chn];
    const float* up = u + (size_t)(b * NH + h) * LEN;
    float* op = g_Yg + (size_t)(b * CHN + chn) * LEN;
    for (int l = threadIdx.x; l < LEN; l += blockDim.x) {
        float yv = R[l].x + up[l] * d;
        float t = tanhf(0.7978845608028654f * (yv + 0.044715f * yv * yv * yv));
        op[l] = 0.5f * yv * (1.f + t);
    }
}

// Kernel 4: fused GEMM + GLU.
// Z[b,l,o] = sum_ch Yg[b,ch,l] * W[ch,o] + bias[o]
// out[b,h,l] = Z[b,l,h] * sigmoid(Z[b,l,h+768])
#define BM 128
#define BN 64
#define BK 16

__global__ void __launch_bounds__(256) gemm_glu_kernel(const float* __restrict__ W,
                                                       const float* __restrict__ bias,
                                                       float* __restrict__ out) {
    __shared__ float As [BK][BM];
    __shared__ float Bs0[BK][BN];
    __shared__ float Bs1[BK][BN];
    int tid = threadIdx.x;
    int m0  = blockIdx.x * BM;       // global m = b*LEN + l
    int b   = m0 / LEN;
    int l0  = m0 - b * LEN;
    int n0  = blockIdx.y * BN;       // h-tile base (0..767)
    const float* Abase = g_Yg + (size_t)b * CHN * LEN + l0;  // A[k][m] = Abase[k*LEN + m]
    int tn = tid & 15;               // 16 threads over N (4 each)
    int tm = tid >> 4;               // 16 threads over M (8 each)
    float acc0[8][4], acc1[8][4];
    #pragma unroll
    for (int i = 0; i < 8; i++)
        #pragma unroll
        for (int j = 0; j < 4; j++) { acc0[i][j] = 0.f; acc1[i][j] = 0.f; }

    int arow = tid >> 5;             // 0..7
    int acol = (tid & 31) * 4;       // 0..124
    int brow = tid >> 4;             // 0..15
    int bcol = (tid & 15) * 4;       // 0..60

    for (int k0 = 0; k0 < CHN; k0 += BK) {
        #pragma unroll
        for (int pp = 0; pp < 2; pp++) {
            int r = arow + pp * 8;
            *(float4*)&As[r][acol] =
                *(const float4*)(Abase + (size_t)(k0 + r) * LEN + acol);
        }
        {
            const float* Wp = W + (size_t)(k0 + brow) * (2 * NH);
            *(float4*)&Bs0[brow][bcol] = *(const float4*)(Wp + n0 + bcol);
            *(float4*)&Bs1[brow][bcol] = *(const float4*)(Wp + n0 + NH + bcol);
        }
        __syncthreads();
        #pragma unroll
        for (int kk = 0; kk < BK; kk++) {
            float a[8], b0[4], b1[4];
            #pragma unroll
            for (int i = 0; i < 8; i++) a[i] = As[kk][tm * 8 + i];
            #pragma unroll
            for (int j = 0; j < 4; j++) {
                b0[j] = Bs0[kk][tn * 4 + j];
                b1[j] = Bs1[kk][tn * 4 + j];
            }
            #pragma unroll
            for (int i = 0; i < 8; i++)
                #pragma unroll
                for (int j = 0; j < 4; j++) {
                    acc0[i][j] += a[i] * b0[j];
                    acc1[i][j] += a[i] * b1[j];
                }
        }
        __syncthreads();
    }

    #pragma unroll
    for (int j = 0; j < 4; j++) {
        int h = n0 + tn * 4 + j;
        float bb0 = bias[h];
        float bb1 = bias[h + NH];
        float* op = out + ((size_t)b * NH + h) * LEN + l0 + tm * 8;
        #pragma unroll
        for (int i = 0; i < 8; i++) {
            float z1 = acc0[i][j] + bb0;
            float z2 = acc1[i][j] + bb1;
            op[i] = z1 / (1.f + expf(-z2));
        }
    }
}

extern "C" void kernel_launch(void* const* d_in, const int* in_sizes, int n_in,
                              void* d_out, int out_size) {
    const float* u    = (const float*)d_in[0];
    const float* D    = (const float*)d_in[1];
    const float* kern = (const float*)d_in[2];
    const float* W    = (const float*)d_in[3];
    const float* bias = (const float*)d_in[4];
    float* out = (float*)d_out;

    int smem = 2 * NFFT * sizeof(float2);   // 128 KB
    cudaFuncSetAttribute(kf_kernel,   cudaFuncAttributeMaxDynamicSharedMemorySize, smem);
    cudaFuncSetAttribute(uf_kernel,   cudaFuncAttributeMaxDynamicSharedMemorySize, smem);
    cudaFuncSetAttribute(conv_kernel, cudaFuncAttributeMaxDynamicSharedMemorySize, smem);

    kf_kernel  <<<CHN,        1024, smem>>>(kern);
    uf_kernel  <<<NB * NH,    1024, smem>>>(u);
    conv_kernel<<<NB * CHN,   1024, smem>>>(u, D);

    dim3 g(NB * LEN / BM, NH / BN);   // (128, 12)
    gemm_glu_kernel<<<g, 256>>>(W, bias, out);
}

// round 3
// speedup vs baseline: 1.7529x; 1.7529x over previous
#include <cuda_runtime.h>
#include <math.h>
#include <stdint.h>

#define LEN   4096
#define NFFT  8192
#define NBF   (NFFT/2)
#define NB    4
#define NC    2
#define NH    768
#define CHN   (NC*NH)          // 1536
#define NOUT  (2*NH)           // 1536
#define NBINS (NFFT/2 + 1)     // 4097
#define LAM   0.1f

// ------------------------- device scratch -------------------------
__device__ float2 g_Kf[(size_t)CHN * NBINS];        // ~50 MB
__device__ float2 g_Uf[(size_t)NB * NH * NBINS];    // ~100 MB
__device__ float  g_Yg[(size_t)NB * CHN * LEN];     // ~100 MB [b][ch][l]

__device__ __forceinline__ float2 cmul(float2 a, float2 b) {
    return make_float2(a.x*b.x - a.y*b.y, a.x*b.y + a.y*b.x);
}

__device__ __forceinline__ uint32_t f2tf32(float v) {
    uint32_t r;
    asm("cvt.rna.tf32.f32 %0, %1;" : "=r"(r) : "f"(v));
    return r;
}

// ------------------------- FFT (Stockham radix-2, n=8192) -------------------------
template<int SIGN>
__device__ float2* fft8192(float2* X, float2* Y) {
    float2* src = X;
    float2* dst = Y;
    int ls = 0;
    #pragma unroll 1
    for (int len = NFFT; len > 1; len >>= 1) {
        int m = len >> 1;
        float theta = (float)SIGN * 6.283185307179586f / (float)len;
        __syncthreads();
        int s = 1 << ls;
        for (int i = threadIdx.x; i < NBF; i += blockDim.x) {
            int p = i >> ls;
            int q = i & (s - 1);
            float2 a = src[q + (p << ls)];
            float2 b = src[q + ((p + m) << ls)];
            float2 sum = make_float2(a.x + b.x, a.y + b.y);
            float2 dif = make_float2(a.x - b.x, a.y - b.y);
            float sn, cs;
            __sincosf(theta * (float)p, &sn, &cs);
            dst[q + ((2*p)   << ls)] = sum;
            dst[q + ((2*p+1) << ls)] = make_float2(dif.x*cs - dif.y*sn,
                                                   dif.x*sn + dif.y*cs);
        }
        float2* t = src; src = dst; dst = t;
        ls++;
    }
    __syncthreads();
    return src;
}

// Kernel 1: soft-threshold + rFFT of conv kernel. grid = C*H
__global__ void __launch_bounds__(1024) kf_kernel(const float* __restrict__ kern) {
    extern __shared__ float2 sm[];
    float2* X = sm;
    float2* Y = sm + NFFT;
    int ch = blockIdx.x;
    const float* kp = kern + (size_t)ch * NFFT;
    for (int i = threadIdx.x; i < NFFT; i += blockDim.x) {
        float x = kp[i];
        float a = fabsf(x) - LAM;
        float v = (a > 0.f) ? copysignf(a, x) : 0.f;
        X[i] = make_float2(v, 0.f);
    }
    float2* R = fft8192<-1>(X, Y);
    float2* dstp = g_Kf + (size_t)ch * NBINS;
    for (int i = threadIdx.x; i < NBINS; i += blockDim.x) dstp[i] = R[i];
}

// Kernel 2: zero-padded rFFT of u. grid = B*H
__global__ void __launch_bounds__(1024) uf_kernel(const float* __restrict__ u) {
    extern __shared__ float2 sm[];
    float2* X = sm;
    float2* Y = sm + NFFT;
    int bh = blockIdx.x;
    const float* up = u + (size_t)bh * LEN;
    for (int i = threadIdx.x; i < NFFT; i += blockDim.x) {
        float v = (i < LEN) ? up[i] : 0.f;
        X[i] = make_float2(v, 0.f);
    }
    float2* R = fft8192<-1>(X, Y);
    float2* dstp = g_Uf + (size_t)bh * NBINS;
    for (int i = threadIdx.x; i < NBINS; i += blockDim.x) dstp[i] = R[i];
}

// Kernel 3: packed spectral product -> ONE iFFT for BOTH c-channels -> skip + GELU.
// grid = B*H. z = y_c0 + i*y_c1, so Z[k] = P0[k] + i*P1[k] over the full spectrum.
__global__ void __launch_bounds__(1024) conv_kernel(const float* __restrict__ u,
                                                    const float* __restrict__ Dm) {
    extern __shared__ float2 sm[];
    float2* X = sm;
    float2* Y = sm + NFFT;
    int bh = blockIdx.x;
    int b  = bh / NH;
    int h  = bh - b * NH;
    const float2* Ufp = g_Uf + (size_t)bh * NBINS;
    const float2* K0p = g_Kf + (size_t)h * NBINS;            // c = 0
    const float2* K1p = g_Kf + (size_t)(NH + h) * NBINS;     // c = 1
    const float scale = 1.0f / (float)NFFT;
    for (int k = threadIdx.x; k < NBINS; k += blockDim.x) {
        float2 U = Ufp[k];
        float2 P0 = cmul(U, K0p[k]);
        float2 P1 = cmul(U, K1p[k]);
        P0.x *= scale; P0.y *= scale; P1.x *= scale; P1.y *= scale;
        // Z[k] = P0 + i*P1
        X[k] = make_float2(P0.x - P1.y, P0.y + P1.x);
        if (k > 0 && k < NBF) {
            // Z[n-k] = conj(P0) + i*conj(P1)
            X[NFFT - k] = make_float2(P0.x + P1.y, P1.x - P0.y);
        }
    }
    float2* R = fft8192<1>(X, Y);
    float d0 = Dm[h];
    float d1 = Dm[NH + h];
    const float* up = u + (size_t)bh * LEN;
    float* o0 = g_Yg + ((size_t)b * CHN + h) * LEN;
    float* o1 = g_Yg + ((size_t)b * CHN + NH + h) * LEN;
    for (int l = threadIdx.x; l < LEN; l += blockDim.x) {
        float uv = up[l];
        float2 z = R[l];
        float y0 = z.x + uv * d0;
        float y1 = z.y + uv * d1;
        float t0 = tanhf(0.7978845608028654f * (y0 + 0.044715f * y0 * y0 * y0));
        float t1 = tanhf(0.7978845608028654f * (y1 + 0.044715f * y1 * y1 * y1));
        o0[l] = 0.5f * y0 * (1.f + t0);
        o1[l] = 0.5f * y1 * (1.f + t1);
    }
}

// ------------------------- tf32 mma.sync GEMM + GLU -------------------------
// Z[m,o] = sum_k Yg[b][k][l] * W[k][o],  m = b*LEN + l (A is naturally K-major!)
// Pseudo-N interleave: pn = 2j   -> numerator o = n0 + j
//                      pn = 2j+1 -> gate      o = n0 + j + NH
// Block: 128 m x 128 pn (64 o-pairs). 8 warps = 4 (m) x 2 (n). Warp: 32 x 64.
#define BM  128
#define BNP 128
#define BK  16
#define ASTR 132           // floats per smem row (pad; 528B rows keep 16B alignment)
#define KITERS (CHN / BK)  // 96

__global__ void __launch_bounds__(256) gemm_glu_mma(const float* __restrict__ W,
                                                    const float* __restrict__ bias,
                                                    float* __restrict__ out) {
    __shared__ float As[2][BK][ASTR];
    __shared__ float Bs[2][BK][ASTR];

    int tid  = threadIdx.x;
    int lane = tid & 31;
    int wid  = tid >> 5;
    int wm   = wid & 3;          // warp m-index: 0..3
    int wn   = wid >> 2;         // warp n-index: 0..1
    int g    = lane >> 2;        // groupID 0..7
    int t    = lane & 3;         // thread-in-group 0..3

    int n0 = blockIdx.x * 64;    // o-tile base (64 outputs per block)
    int m0 = blockIdx.y * BM;    // global m base
    int b  = m0 >> 12;
    int l0 = m0 & (LEN - 1);

    const float* Abase = g_Yg + ((size_t)b * CHN) * LEN + l0;   // + k*LEN + m

    // per-thread ldg assignments (512 float4 per tile, 2 per thread)
    int fidA0 = tid, fidA1 = tid + 256;
    float4 av[2], bv[2];

    float c[2][8][4];
    #pragma unroll
    for (int mi = 0; mi < 2; mi++)
        #pragma unroll
        for (int ni = 0; ni < 8; ni++)
            #pragma unroll
            for (int q = 0; q < 4; q++) c[mi][ni][q] = 0.f;

    // ---- tile load helpers (as lambdas via macros) ----
    #define LDG_TILE(k0)                                                          \
    {                                                                             \
        int ka0 = fidA0 >> 5, ma0 = (fidA0 & 31) * 4;                             \
        int ka1 = fidA1 >> 5, ma1 = (fidA1 & 31) * 4;                             \
        av[0] = *(const float4*)(Abase + (size_t)((k0) + ka0) * LEN + ma0);       \
        av[1] = *(const float4*)(Abase + (size_t)((k0) + ka1) * LEN + ma1);       \
        int kb0 = fidA0 >> 5, q0 = fidA0 & 31;                                    \
        int kb1 = fidA1 >> 5, q1 = fidA1 & 31;                                    \
        int o0q = (q0 < 16) ? (n0 + q0 * 4) : (NH + n0 + (q0 - 16) * 4);          \
        int o1q = (q1 < 16) ? (n0 + q1 * 4) : (NH + n0 + (q1 - 16) * 4);          \
        bv[0] = *(const float4*)(W + (size_t)((k0) + kb0) * NOUT + o0q);          \
        bv[1] = *(const float4*)(W + (size_t)((k0) + kb1) * NOUT + o1q);          \
    }

    #define STS_TILE(buf)                                                         \
    {                                                                             \
        int ka0 = fidA0 >> 5, ma0 = (fidA0 & 31) * 4;                             \
        int ka1 = fidA1 >> 5, ma1 = (fidA1 & 31) * 4;                             \
        uint32_t* ap0 = (uint32_t*)&As[buf][ka0][ma0];                            \
        ap0[0] = f2tf32(av[0].x); ap0[1] = f2tf32(av[0].y);                       \
        ap0[2] = f2tf32(av[0].z); ap0[3] = f2tf32(av[0].w);                       \
        uint32_t* ap1 = (uint32_t*)&As[buf][ka1][ma1];                            \
        ap1[0] = f2tf32(av[1].x); ap1[1] = f2tf32(av[1].y);                       \
        ap1[2] = f2tf32(av[1].z); ap1[3] = f2tf32(av[1].w);                       \
        int kb0 = fidA0 >> 5, q0 = fidA0 & 31;                                    \
        int kb1 = fidA1 >> 5, q1 = fidA1 & 31;                                    \
        int s0 = (q0 < 16) ? 0 : 1; int j0 = (q0 < 16) ? q0 * 4 : (q0 - 16) * 4;  \
        int s1 = (q1 < 16) ? 0 : 1; int j1 = (q1 < 16) ? q1 * 4 : (q1 - 16) * 4;  \
        uint32_t* bp = (uint32_t*)&Bs[buf][kb0][0];                               \
        bp[2*j0 + s0]     = f2tf32(bv[0].x);                                      \
        bp[2*(j0+1) + s0] = f2tf32(bv[0].y);                                      \
        bp[2*(j0+2) + s0] = f2tf32(bv[0].z);                                      \
        bp[2*(j0+3) + s0] = f2tf32(bv[0].w);                                      \
        uint32_t* bq = (uint32_t*)&Bs[buf][kb1][0];                               \
        bq[2*j1 + s1]     = f2tf32(bv[1].x);                                      \
        bq[2*(j1+1) + s1] = f2tf32(bv[1].y);                                      \
        bq[2*(j1+2) + s1] = f2tf32(bv[1].z);                                      \
        bq[2*(j1+3) + s1] = f2tf32(bv[1].w);                                      \
    }

    LDG_TILE(0);
    STS_TILE(0);
    __syncthreads();

    #pragma unroll 1
    for (int it = 0; it < KITERS; it++) {
        int cur = it & 1;
        if (it + 1 < KITERS) LDG_TILE((it + 1) * BK);

        const uint32_t* Asm = (const uint32_t*)&As[cur][0][0];
        const uint32_t* Bsm = (const uint32_t*)&Bs[cur][0][0];
        #pragma unroll
        for (int ks = 0; ks < 2; ks++) {
            int kb = ks * 8;
            uint32_t af[2][4];
            #pragma unroll
            for (int mi = 0; mi < 2; mi++) {
                int mrow = wm * 32 + mi * 16;
                af[mi][0] = Asm[(kb + t)     * ASTR + mrow + g];
                af[mi][1] = Asm[(kb + t)     * ASTR + mrow + g + 8];
                af[mi][2] = Asm[(kb + t + 4) * ASTR + mrow + g];
                af[mi][3] = Asm[(kb + t + 4) * ASTR + mrow + g + 8];
            }
            #pragma unroll
            for (int ni = 0; ni < 8; ni++) {
                int ncol = wn * 64 + ni * 8 + g;
                uint32_t b0 = Bsm[(kb + t)     * ASTR + ncol];
                uint32_t b1 = Bsm[(kb + t + 4) * ASTR + ncol];
                #pragma unroll
                for (int mi = 0; mi < 2; mi++) {
                    asm volatile(
                        "mma.sync.aligned.m16n8k8.row.col.f32.tf32.tf32.f32 "
                        "{%0,%1,%2,%3}, {%4,%5,%6,%7}, {%8,%9}, {%0,%1,%2,%3};"
                        : "+f"(c[mi][ni][0]), "+f"(c[mi][ni][1]),
                          "+f"(c[mi][ni][2]), "+f"(c[mi][ni][3])
                        : "r"(af[mi][0]), "r"(af[mi][1]), "r"(af[mi][2]), "r"(af[mi][3]),
                          "r"(b0), "r"(b1));
                }
            }
        }
        if (it + 1 < KITERS) STS_TILE(1 - cur);
        __syncthreads();
    }

    // ---- epilogue: GLU pairs live in (c0,c1) and (c2,c3) of each thread ----
    #pragma unroll
    for (int ni = 0; ni < 8; ni++) {
        int o = n0 + wn * 32 + ni * 4 + t;
        float bb0 = bias[o];
        float bb1 = bias[o + NH];
        float* orow = out + ((size_t)b * NH + o) * LEN;
        #pragma unroll
        for (int mi = 0; mi < 2; mi++) {
            int l = l0 + wm * 32 + mi * 16 + g;
            float z1 = c[mi][ni][0] + bb0;
            float z2 = c[mi][ni][1] + bb1;
            orow[l] = z1 / (1.f + __expf(-z2));
            float z3 = c[mi][ni][2] + bb0;
            float z4 = c[mi][ni][3] + bb1;
            orow[l + 8] = z3 / (1.f + __expf(-z4));
        }
    }
}

// ------------------------- launch -------------------------
extern "C" void kernel_launch(void* const* d_in, const int* in_sizes, int n_in,
                              void* d_out, int out_size) {
    const float* u    = (const float*)d_in[0];
    const float* D    = (const float*)d_in[1];
    const float* kern = (const float*)d_in[2];
    const float* W    = (const float*)d_in[3];
    const float* bias = (const float*)d_in[4];
    float* out = (float*)d_out;

    int smemF = 2 * NFFT * sizeof(float2);   // 128 KB
    cudaFuncSetAttribute(kf_kernel,   cudaFuncAttributeMaxDynamicSharedMemorySize, smemF);
    cudaFuncSetAttribute(uf_kernel,   cudaFuncAttributeMaxDynamicSharedMemorySize, smemF);
    cudaFuncSetAttribute(conv_kernel, cudaFuncAttributeMaxDynamicSharedMemorySize, smemF);

    kf_kernel  <<<CHN,     1024, smemF>>>(kern);
    uf_kernel  <<<NB * NH, 1024, smemF>>>(u);
    conv_kernel<<<NB * NH, 1024, smemF>>>(u, D);

    dim3 g(NH / 64, NB * LEN / BM);   // (12, 128); x = n inner for A L2 reuse
    gemm_glu_mma<<<g, 256>>>(W, bias, out);
}

// round 5
// speedup vs baseline: 1.9707x; 1.1242x over previous
#include <cuda_runtime.h>
#include <math.h>
#include <stdint.h>

#define LEN   4096
#define NFFT  8192
#define NBF   (NFFT/2)
#define NB    4
#define NC    2
#define NH    768
#define CHN   (NC*NH)          // 1536
#define NOUT  (2*NH)           // 1536
#define NBINS (NFFT/2 + 1)     // 4097
#define LAM   0.1f

// ------------------------- device scratch -------------------------
__device__ float2 g_Kf[(size_t)CHN * NBINS];        // ~50 MB
__device__ float2 g_Uf[(size_t)NB * NH * NBINS];    // ~100 MB
__device__ float  g_Yg[(size_t)NB * CHN * LEN];     // ~100 MB [b][ch][l]

__device__ __forceinline__ float2 cmul(float2 a, float2 b) {
    return make_float2(a.x*b.x - a.y*b.y, a.x*b.y + a.y*b.x);
}
__device__ __forceinline__ float2 cadd(float2 a, float2 b) {
    return make_float2(a.x + b.x, a.y + b.y);
}
__device__ __forceinline__ float2 csub(float2 a, float2 b) {
    return make_float2(a.x - b.x, a.y - b.y);
}
__device__ __forceinline__ uint32_t f2tf32(float v) {
    uint32_t r;
    asm("cvt.rna.tf32.f32 %0, %1;" : "=r"(r) : "f"(v));
    return r;
}

// ---------------- FFT: radix-4 Stockham, n=8192 (6 r4 stages + 1 r2) ----------------
template<int SIGN>
__device__ float2* fft8192(float2* X, float2* Y) {
    float2* src = X;
    float2* dst = Y;
    int ls = 0;
    #pragma unroll 1
    for (int len = NFFT; len >= 4; len >>= 2) {
        float theta = (float)SIGN * 6.283185307179586f / (float)len;
        __syncthreads();
        int s = 1 << ls;
        #pragma unroll 1
        for (int i = threadIdx.x; i < NFFT / 4; i += blockDim.x) {
            int p = i >> ls;
            int q = i & (s - 1);
            int base = q + p * s;
            float2 a0 = src[base];
            float2 a1 = src[base + 2048];
            float2 a2 = src[base + 4096];
            float2 a3 = src[base + 6144];
            float2 t0 = cadd(a0, a2), t1 = cadd(a1, a3);
            float2 t2 = csub(a0, a2), t3 = csub(a1, a3);
            float2 j3 = (SIGN < 0) ? make_float2(t3.y, -t3.x)
                                   : make_float2(-t3.y, t3.x);
            float2 b0 = cadd(t0, t1);
            float2 b1 = cadd(t2, j3);
            float2 b2 = csub(t0, t1);
            float2 b3 = csub(t2, j3);
            float sn, cs;
            __sincosf(theta * (float)p, &sn, &cs);
            float2 w1 = make_float2(cs, sn);
            float2 w2 = cmul(w1, w1);
            float2 w3 = cmul(w2, w1);
            int db = q + (p << (ls + 2));
            dst[db]         = b0;
            dst[db + s]     = cmul(b1, w1);
            dst[db + 2*s]   = cmul(b2, w2);
            dst[db + 3*s]   = cmul(b3, w3);
        }
        float2* t = src; src = dst; dst = t;
        ls += 2;
    }
    // final radix-2 stage: len=2, s=4096, twiddle=1
    __syncthreads();
    for (int i = threadIdx.x; i < NBF; i += blockDim.x) {
        float2 a = src[i];
        float2 b = src[i + NBF];
        dst[i]       = cadd(a, b);
        dst[i + NBF] = csub(a, b);
    }
    __syncthreads();
    return dst;
}

// Kernel 1: soft-threshold + PACKED rFFT of conv kernel (2 channels/block). grid = CHN/2
__global__ void __launch_bounds__(1024) kf2_kernel(const float* __restrict__ kern) {
    extern __shared__ float2 sm[];
    float2* X = sm;
    float2* Y = sm + NFFT;
    int ch0 = blockIdx.x * 2;
    const float* k0p = kern + (size_t)ch0 * NFFT;
    const float* k1p = k0p + NFFT;
    for (int i = threadIdx.x; i < NFFT; i += blockDim.x) {
        float x0 = k0p[i], x1 = k1p[i];
        float a0 = fabsf(x0) - LAM, a1 = fabsf(x1) - LAM;
        float v0 = (a0 > 0.f) ? copysignf(a0, x0) : 0.f;
        float v1 = (a1 > 0.f) ? copysignf(a1, x1) : 0.f;
        X[i] = make_float2(v0, v1);
    }
    float2* R = fft8192<-1>(X, Y);
    float2* d0 = g_Kf + (size_t)ch0 * NBINS;
    float2* d1 = d0 + NBINS;
    for (int k = threadIdx.x; k < NBF; k += blockDim.x) {
        if (k == 0) {
            d0[0]    = make_float2(R[0].x, 0.f);
            d1[0]    = make_float2(R[0].y, 0.f);
            d0[NBF]  = make_float2(R[NBF].x, 0.f);
            d1[NBF]  = make_float2(R[NBF].y, 0.f);
        } else {
            float2 Zk = R[k], Zm = R[NFFT - k];
            d0[k] = make_float2(0.5f * (Zk.x + Zm.x), 0.5f * (Zk.y - Zm.y));
            d1[k] = make_float2(0.5f * (Zk.y + Zm.y), 0.5f * (Zm.x - Zk.x));
        }
    }
}

// Kernel 2: PACKED zero-padded rFFT of u (2 h-channels/block). grid = NB*NH/2
__global__ void __launch_bounds__(1024) uf2_kernel(const float* __restrict__ u) {
    extern __shared__ float2 sm[];
    float2* X = sm;
    float2* Y = sm + NFFT;
    int b  = blockIdx.x / (NH / 2);
    int hp = blockIdx.x % (NH / 2);
    int h0 = hp * 2;
    const float* u0 = u + ((size_t)b * NH + h0) * LEN;
    const float* u1 = u0 + LEN;
    for (int i = threadIdx.x; i < NFFT; i += blockDim.x) {
        float v0 = (i < LEN) ? u0[i] : 0.f;
        float v1 = (i < LEN) ? u1[i] : 0.f;
        X[i] = make_float2(v0, v1);
    }
    float2* R = fft8192<-1>(X, Y);
    float2* d0 = g_Uf + ((size_t)b * NH + h0) * NBINS;
    float2* d1 = d0 + NBINS;
    for (int k = threadIdx.x; k < NBF; k += blockDim.x) {
        if (k == 0) {
            d0[0]    = make_float2(R[0].x, 0.f);
            d1[0]    = make_float2(R[0].y, 0.f);
            d0[NBF]  = make_float2(R[NBF].x, 0.f);
            d1[NBF]  = make_float2(R[NBF].y, 0.f);
        } else {
            float2 Zk = R[k], Zm = R[NFFT - k];
            d0[k] = make_float2(0.5f * (Zk.x + Zm.x), 0.5f * (Zk.y - Zm.y));
            d1[k] = make_float2(0.5f * (Zk.y + Zm.y), 0.5f * (Zm.x - Zk.x));
        }
    }
}

// Kernel 3: packed spectral product -> ONE iFFT for BOTH c-channels -> skip + GELU.
// grid = B*H. z = y_c0 + i*y_c1.
__global__ void __launch_bounds__(1024) conv_kernel(const float* __restrict__ u,
                                                    const float* __restrict__ Dm) {
    extern __shared__ float2 sm[];
    float2* X = sm;
    float2* Y = sm + NFFT;
    int bh = blockIdx.x;
    int b  = bh / NH;
    int h  = bh - b * NH;
    const float2* Ufp = g_Uf + (size_t)bh * NBINS;
    const float2* K0p = g_Kf + (size_t)h * NBINS;            // c = 0
    const float2* K1p = g_Kf + (size_t)(NH + h) * NBINS;     // c = 1
    const float scale = 1.0f / (float)NFFT;
    for (int k = threadIdx.x; k < NBINS; k += blockDim.x) {
        float2 U = Ufp[k];
        float2 P0 = cmul(U, K0p[k]);
        float2 P1 = cmul(U, K1p[k]);
        P0.x *= scale; P0.y *= scale; P1.x *= scale; P1.y *= scale;
        X[k] = make_float2(P0.x - P1.y, P0.y + P1.x);
        if (k > 0 && k < NBF) {
            X[NFFT - k] = make_float2(P0.x + P1.y, P1.x - P0.y);
        }
    }
    float2* R = fft8192<1>(X, Y);
    float d0 = Dm[h];
    float d1 = Dm[NH + h];
    const float* up = u + (size_t)bh * LEN;
    float* o0 = g_Yg + ((size_t)b * CHN + h) * LEN;
    float* o1 = g_Yg + ((size_t)b * CHN + NH + h) * LEN;
    for (int l = threadIdx.x; l < LEN; l += blockDim.x) {
        float uv = up[l];
        float2 z = R[l];
        float y0 = z.x + uv * d0;
        float y1 = z.y + uv * d1;
        float t0 = tanhf(0.7978845608028654f * (y0 + 0.044715f * y0 * y0 * y0));
        float t1 = tanhf(0.7978845608028654f * (y1 + 0.044715f * y1 * y1 * y1));
        o0[l] = 0.5f * y0 * (1.f + t0);
        o1[l] = 0.5f * y1 * (1.f + t1);
    }
}

// ------------------------- tf32 mma.sync GEMM + GLU -------------------------
// Z[m,o] = sum_k Yg[b][k][l] * W[k][o],  m = b*LEN + l
// Pseudo-N interleave: pn=2j -> o=n0+j (numerator), pn=2j+1 -> o=NH+n0+j (gate).
// Block 128m x 128pn. 8 warps = 4(m) x 2(n). Warp tile 32m x 64pn.
// Smem: [row][16 k-floats] per tile, k stored permuted: slot = k&3, elem = k>>2,
// phys slot = slot ^ ((row ^ (row>>2)) & 3)  -> conflict-free LDS.128 + STS.128.
#define BM 128
#define BK 16
#define KITERS (CHN / BK)  // 96

__global__ void __launch_bounds__(256) gemm_glu_mma(const float* __restrict__ W,
                                                    const float* __restrict__ bias,
                                                    float* __restrict__ out) {
    __shared__ float As[2][BM * BK];
    __shared__ float Bs[2][BM * BK];

    int tid  = threadIdx.x;
    int lane = tid & 31;
    int wid  = tid >> 5;
    int wm   = wid & 3;          // warp m-index 0..3
    int wn   = wid >> 2;         // warp n-index 0..1
    int g    = lane >> 2;        // group 0..7
    int t    = lane & 3;         // thread-in-group 0..3

    int n0 = blockIdx.x * 64;    // o-tile base
    int m0 = blockIdx.y * BM;
    int b  = m0 >> 12;
    int l0 = m0 & (LEN - 1);

    // ---- loader assignment: row = tid&127 (both A-m and B-pn), 2 slots each ----
    int lrow = tid & 127;
    int sh   = tid >> 7;          // 0..1
    int s0   = 2 * sh, s1 = 2 * sh + 1;
    int lswz = (lrow ^ (lrow >> 2)) & 3;
    int stA0 = lrow * 16 + ((s0 ^ lswz) << 2);
    int stA1 = lrow * 16 + ((s1 ^ lswz) << 2);

    const float* Ag = g_Yg + (size_t)b * CHN * LEN + l0 + lrow;     // + k*LEN
    int og = (lrow & 1) ? (NH + n0 + (lrow >> 1)) : (n0 + (lrow >> 1));
    const float* Bg = W + og;                                        // + k*NOUT

    // ---- fragment offsets (loop-invariant) ----
    int aoff[2][2], boff[8];
    #pragma unroll
    for (int mi = 0; mi < 2; mi++) {
        int r0 = wm * 32 + mi * 16 + g;
        int r1 = r0 + 8;
        aoff[mi][0] = r0 * 16 + ((t ^ ((r0 ^ (r0 >> 2)) & 3)) << 2);
        aoff[mi][1] = r1 * 16 + ((t ^ ((r1 ^ (r1 >> 2)) & 3)) << 2);
    }
    #pragma unroll
    for (int ni = 0; ni < 8; ni++) {
        int rb = wn * 64 + ni * 8 + g;
        boff[ni] = rb * 16 + ((t ^ ((rb ^ (rb >> 2)) & 3)) << 2);
    }

    float c[2][8][4];
    #pragma unroll
    for (int mi = 0; mi < 2; mi++)
        #pragma unroll
        for (int ni = 0; ni < 8; ni++)
            #pragma unroll
            for (int q = 0; q < 4; q++) c[mi][ni][q] = 0.f;

    float ar0[4], ar1[4], br0[4], br1[4];

    #define LDG_TILE(k0)                                          \
    {                                                             \
        const float* ap = Ag + (size_t)(k0) * LEN;                \
        const float* bp = Bg + (size_t)(k0) * NOUT;               \
        _Pragma("unroll")                                         \
        for (int e = 0; e < 4; e++) {                             \
            ar0[e] = ap[(size_t)(s0 + 4*e) * LEN];                \
            ar1[e] = ap[(size_t)(s1 + 4*e) * LEN];                \
            br0[e] = bp[(size_t)(s0 + 4*e) * NOUT];               \
            br1[e] = bp[(size_t)(s1 + 4*e) * NOUT];               \
        }                                                         \
    }

    #define STS_TILE(buf)                                         \
    {                                                             \
        uint4 v;                                                  \
        v.x = f2tf32(ar0[0]); v.y = f2tf32(ar0[1]);               \
        v.z = f2tf32(ar0[2]); v.w = f2tf32(ar0[3]);               \
        *(uint4*)&As[buf][stA0] = v;                              \
        v.x = f2tf32(ar1[0]); v.y = f2tf32(ar1[1]);               \
        v.z = f2tf32(ar1[2]); v.w = f2tf32(ar1[3]);               \
        *(uint4*)&As[buf][stA1] = v;                              \
        v.x = f2tf32(br0[0]); v.y = f2tf32(br0[1]);               \
        v.z = f2tf32(br0[2]); v.w = f2tf32(br0[3]);               \
        *(uint4*)&Bs[buf][stA0] = v;                              \
        v.x = f2tf32(br1[0]); v.y = f2tf32(br1[1]);               \
        v.z = f2tf32(br1[2]); v.w = f2tf32(br1[3]);               \
        *(uint4*)&Bs[buf][stA1] = v;                              \
    }

    LDG_TILE(0);
    STS_TILE(0);
    __syncthreads();

    #pragma unroll 1
    for (int it = 0; it < KITERS; it++) {
        int cur = it & 1;
        if (it + 1 < KITERS) LDG_TILE((it + 1) * BK);

        const float* Ab = As[cur];
        const float* Bb = Bs[cur];
        uint4 va[2][2];
        #pragma unroll
        for (int mi = 0; mi < 2; mi++) {
            va[mi][0] = *(const uint4*)&Ab[aoff[mi][0]];
            va[mi][1] = *(const uint4*)&Ab[aoff[mi][1]];
        }
        #pragma unroll
        for (int ni = 0; ni < 8; ni++) {
            uint4 vb = *(const uint4*)&Bb[boff[ni]];
            #pragma unroll
            for (int mi = 0; mi < 2; mi++) {
                asm volatile(
                    "mma.sync.aligned.m16n8k8.row.col.f32.tf32.tf32.f32 "
                    "{%0,%1,%2,%3}, {%4,%5,%6,%7}, {%8,%9}, {%0,%1,%2,%3};"
                    : "+f"(c[mi][ni][0]), "+f"(c[mi][ni][1]),
                      "+f"(c[mi][ni][2]), "+f"(c[mi][ni][3])
                    : "r"(va[mi][0].x), "r"(va[mi][1].x),
                      "r"(va[mi][0].y), "r"(va[mi][1].y),
                      "r"(vb.x), "r"(vb.y));
                asm volatile(
                    "mma.sync.aligned.m16n8k8.row.col.f32.tf32.tf32.f32 "
                    "{%0,%1,%2,%3}, {%4,%5,%6,%7}, {%8,%9}, {%0,%1,%2,%3};"
                    : "+f"(c[mi][ni][0]), "+f"(c[mi][ni][1]),
                      "+f"(c[mi][ni][2]), "+f"(c[mi][ni][3])
                    : "r"(va[mi][0].z), "r"(va[mi][1].z),
                      "r"(va[mi][0].w), "r"(va[mi][1].w),
                      "r"(vb.z), "r"(vb.w));
            }
        }
        if (it + 1 < KITERS) STS_TILE(1 - cur);
        __syncthreads();
    }

    // ---- epilogue: GLU pairs in (c0,c1) and (c2,c3) ----
    #pragma unroll
    for (int ni = 0; ni < 8; ni++) {
        int o = n0 + wn * 32 + ni * 4 + t;
        float bb0 = bias[o];
        float bb1 = bias[o + NH];
        float* orow = out + ((size_t)b * NH + o) * LEN;
        #pragma unroll
        for (int mi = 0; mi < 2; mi++) {
            int l = l0 + wm * 32 + mi * 16 + g;
            float z1 = c[mi][ni][0] + bb0;
            float z2 = c[mi][ni][1] + bb1;
            orow[l] = z1 / (1.f + __expf(-z2));
            float z3 = c[mi][ni][2] + bb0;
            float z4 = c[mi][ni][3] + bb1;
            orow[l + 8] = z3 / (1.f + __expf(-z4));
        }
    }
}

// ------------------------- launch -------------------------
extern "C" void kernel_launch(void* const* d_in, const int* in_sizes, int n_in,
                              void* d_out, int out_size) {
    const float* u    = (const float*)d_in[0];
    const float* D    = (const float*)d_in[1];
    const float* kern = (const float*)d_in[2];
    const float* W    = (const float*)d_in[3];
    const float* bias = (const float*)d_in[4];
    float* out = (float*)d_out;

    int smemF = 2 * NFFT * sizeof(float2);   // 128 KB
    cudaFuncSetAttribute(kf2_kernel,  cudaFuncAttributeMaxDynamicSharedMemorySize, smemF);
    cudaFuncSetAttribute(uf2_kernel,  cudaFuncAttributeMaxDynamicSharedMemorySize, smemF);
    cudaFuncSetAttribute(conv_kernel, cudaFuncAttributeMaxDynamicSharedMemorySize, smemF);

    kf2_kernel <<<CHN / 2,       1024, smemF>>>(kern);
    uf2_kernel <<<NB * NH / 2,   1024, smemF>>>(u);
    conv_kernel<<<NB * NH,       1024, smemF>>>(u, D);

    dim3 g(NH / 64, NB * LEN / BM);   // (12, 128)
    gemm_glu_mma<<<g, 256>>>(W, bias, out);
}

// round 6
// speedup vs baseline: 2.6710x; 1.3554x over previous
#include <cuda_runtime.h>
#include <math.h>
#include <stdint.h>

#define LEN   4096
#define NFFT  8192
#define NBF   (NFFT/2)
#define NB    4
#define NC    2
#define NH    768
#define CHN   (NC*NH)          // 1536
#define NOUT  (2*NH)           // 1536
#define NBINS (NFFT/2 + 1)     // 4097
#define LAM   0.1f

// ------------------------- device scratch -------------------------
__device__ float2 g_Kf[(size_t)CHN * NBINS];        // ~50 MB
__device__ float2 g_Uf[(size_t)NB * NH * NBINS];    // ~100 MB
__device__ float  g_Yg[(size_t)NB * CHN * LEN];     // ~100 MB [b][ch][l] (tf32-rounded)
__device__ float  g_Wr[(size_t)CHN * NOUT];         // ~9.4 MB tf32-rounded W

__device__ __forceinline__ float2 cmul(float2 a, float2 b) {
    return make_float2(a.x*b.x - a.y*b.y, a.x*b.y + a.y*b.x);
}
__device__ __forceinline__ float2 cadd(float2 a, float2 b) {
    return make_float2(a.x + b.x, a.y + b.y);
}
__device__ __forceinline__ float2 csub(float2 a, float2 b) {
    return make_float2(a.x - b.x, a.y - b.y);
}
__device__ __forceinline__ float f2tf32f(float v) {
    uint32_t r;
    asm("cvt.rna.tf32.f32 %0, %1;" : "=r"(r) : "f"(v));
    return __uint_as_float(r);
}

// ---------------- FFT: radix-4 Stockham, n=8192 (6 r4 stages + 1 r2) ----------------
template<int SIGN>
__device__ float2* fft8192(float2* X, float2* Y) {
    float2* src = X;
    float2* dst = Y;
    int ls = 0;
    #pragma unroll 1
    for (int len = NFFT; len >= 4; len >>= 2) {
        float theta = (float)SIGN * 6.283185307179586f / (float)len;
        __syncthreads();
        int s = 1 << ls;
        #pragma unroll 1
        for (int i = threadIdx.x; i < NFFT / 4; i += blockDim.x) {
            int p = i >> ls;
            int q = i & (s - 1);
            int base = q + p * s;
            float2 a0 = src[base];
            float2 a1 = src[base + 2048];
            float2 a2 = src[base + 4096];
            float2 a3 = src[base + 6144];
            float2 t0 = cadd(a0, a2), t1 = cadd(a1, a3);
            float2 t2 = csub(a0, a2), t3 = csub(a1, a3);
            float2 j3 = (SIGN < 0) ? make_float2(t3.y, -t3.x)
                                   : make_float2(-t3.y, t3.x);
            float2 b0 = cadd(t0, t1);
            float2 b1 = cadd(t2, j3);
            float2 b2 = csub(t0, t1);
            float2 b3 = csub(t2, j3);
            float sn, cs;
            __sincosf(theta * (float)p, &sn, &cs);
            float2 w1 = make_float2(cs, sn);
            float2 w2 = cmul(w1, w1);
            float2 w3 = cmul(w2, w1);
            int db = q + (p << (ls + 2));
            dst[db]         = b0;
            dst[db + s]     = cmul(b1, w1);
            dst[db + 2*s]   = cmul(b2, w2);
            dst[db + 3*s]   = cmul(b3, w3);
        }
        float2* t = src; src = dst; dst = t;
        ls += 2;
    }
    // final radix-2 stage
    __syncthreads();
    for (int i = threadIdx.x; i < NBF; i += blockDim.x) {
        float2 a = src[i];
        float2 b = src[i + NBF];
        dst[i]       = cadd(a, b);
        dst[i + NBF] = csub(a, b);
    }
    __syncthreads();
    return dst;
}

// Kernel 1: soft-threshold + PACKED rFFT of conv kernel (2 channels/block). grid = CHN/2
__global__ void __launch_bounds__(1024) kf2_kernel(const float* __restrict__ kern) {
    extern __shared__ float2 sm[];
    float2* X = sm;
    float2* Y = sm + NFFT;
    int ch0 = blockIdx.x * 2;
    const float* k0p = kern + (size_t)ch0 * NFFT;
    const float* k1p = k0p + NFFT;
    for (int i = threadIdx.x; i < NFFT; i += blockDim.x) {
        float x0 = k0p[i], x1 = k1p[i];
        float a0 = fabsf(x0) - LAM, a1 = fabsf(x1) - LAM;
        float v0 = (a0 > 0.f) ? copysignf(a0, x0) : 0.f;
        float v1 = (a1 > 0.f) ? copysignf(a1, x1) : 0.f;
        X[i] = make_float2(v0, v1);
    }
    float2* R = fft8192<-1>(X, Y);
    float2* d0 = g_Kf + (size_t)ch0 * NBINS;
    float2* d1 = d0 + NBINS;
    for (int k = threadIdx.x; k < NBF; k += blockDim.x) {
        if (k == 0) {
            d0[0]    = make_float2(R[0].x, 0.f);
            d1[0]    = make_float2(R[0].y, 0.f);
            d0[NBF]  = make_float2(R[NBF].x, 0.f);
            d1[NBF]  = make_float2(R[NBF].y, 0.f);
        } else {
            float2 Zk = R[k], Zm = R[NFFT - k];
            d0[k] = make_float2(0.5f * (Zk.x + Zm.x), 0.5f * (Zk.y - Zm.y));
            d1[k] = make_float2(0.5f * (Zk.y + Zm.y), 0.5f * (Zm.x - Zk.x));
        }
    }
}

// Kernel 2: PACKED zero-padded rFFT of u (2 h-channels/block). grid = NB*NH/2
__global__ void __launch_bounds__(1024) uf2_kernel(const float* __restrict__ u) {
    extern __shared__ float2 sm[];
    float2* X = sm;
    float2* Y = sm + NFFT;
    int b  = blockIdx.x / (NH / 2);
    int hp = blockIdx.x % (NH / 2);
    int h0 = hp * 2;
    const float* u0 = u + ((size_t)b * NH + h0) * LEN;
    const float* u1 = u0 + LEN;
    for (int i = threadIdx.x; i < NFFT; i += blockDim.x) {
        float v0 = (i < LEN) ? u0[i] : 0.f;
        float v1 = (i < LEN) ? u1[i] : 0.f;
        X[i] = make_float2(v0, v1);
    }
    float2* R = fft8192<-1>(X, Y);
    float2* d0 = g_Uf + ((size_t)b * NH + h0) * NBINS;
    float2* d1 = d0 + NBINS;
    for (int k = threadIdx.x; k < NBF; k += blockDim.x) {
        if (k == 0) {
            d0[0]    = make_float2(R[0].x, 0.f);
            d1[0]    = make_float2(R[0].y, 0.f);
            d0[NBF]  = make_float2(R[NBF].x, 0.f);
            d1[NBF]  = make_float2(R[NBF].y, 0.f);
        } else {
            float2 Zk = R[k], Zm = R[NFFT - k];
            d0[k] = make_float2(0.5f * (Zk.x + Zm.x), 0.5f * (Zk.y - Zm.y));
            d1[k] = make_float2(0.5f * (Zk.y + Zm.y), 0.5f * (Zm.x - Zk.x));
        }
    }
}

// Kernel 3: packed spectral product -> ONE iFFT for BOTH c-channels -> skip + GELU
// (output tf32-rounded for the MMA). grid = B*H.
__global__ void __launch_bounds__(1024) conv_kernel(const float* __restrict__ u,
                                                    const float* __restrict__ Dm) {
    extern __shared__ float2 sm[];
    float2* X = sm;
    float2* Y = sm + NFFT;
    int bh = blockIdx.x;
    int b  = bh / NH;
    int h  = bh - b * NH;
    const float2* Ufp = g_Uf + (size_t)bh * NBINS;
    const float2* K0p = g_Kf + (size_t)h * NBINS;            // c = 0
    const float2* K1p = g_Kf + (size_t)(NH + h) * NBINS;     // c = 1
    const float scale = 1.0f / (float)NFFT;
    for (int k = threadIdx.x; k < NBINS; k += blockDim.x) {
        float2 U = Ufp[k];
        float2 P0 = cmul(U, K0p[k]);
        float2 P1 = cmul(U, K1p[k]);
        P0.x *= scale; P0.y *= scale; P1.x *= scale; P1.y *= scale;
        X[k] = make_float2(P0.x - P1.y, P0.y + P1.x);
        if (k > 0 && k < NBF) {
            X[NFFT - k] = make_float2(P0.x + P1.y, P1.x - P0.y);
        }
    }
    float2* R = fft8192<1>(X, Y);
    float d0 = Dm[h];
    float d1 = Dm[NH + h];
    const float* up = u + (size_t)bh * LEN;
    float* o0 = g_Yg + ((size_t)b * CHN + h) * LEN;
    float* o1 = g_Yg + ((size_t)b * CHN + NH + h) * LEN;
    for (int l = threadIdx.x; l < LEN; l += blockDim.x) {
        float uv = up[l];
        float2 z = R[l];
        float y0 = z.x + uv * d0;
        float y1 = z.y + uv * d1;
        float t0 = tanhf(0.7978845608028654f * (y0 + 0.044715f * y0 * y0 * y0));
        float t1 = tanhf(0.7978845608028654f * (y1 + 0.044715f * y1 * y1 * y1));
        o0[l] = f2tf32f(0.5f * y0 * (1.f + t0));
        o1[l] = f2tf32f(0.5f * y1 * (1.f + t1));
    }
}

// Kernel 3b: pre-round W to tf32.
__global__ void __launch_bounds__(256) wround_kernel(const float* __restrict__ W) {
    int i = blockIdx.x * 256 + threadIdx.x;
    g_Wr[i] = f2tf32f(W[i]);
}

// ------------------------- tf32 mma.sync GEMM + GLU -------------------------
// Z[m,o] = sum_k Yg[b][k][l] * Wr[k][o],  m = b*LEN + l
// Pseudo-N interleave: pn=2j -> o=n0+j (numerator), pn=2j+1 -> o=NH+n0+j (gate).
// Block 128m x 128pn. 8 warps = 4(m) x 2(n). Warp tile 32m x 64pn.
// Smem rows [row][16 k-floats], slot xor-swizzled -> conflict-free LDS.128/STS.128.
#define BM 128
#define BK 16
#define KITERS (CHN / BK)  // 96

__global__ void __launch_bounds__(256, 2) gemm_glu_mma(const float* __restrict__ bias,
                                                       float* __restrict__ out) {
    __shared__ float As[2][BM * BK];
    __shared__ float Bs[2][BM * BK];

    int tid  = threadIdx.x;
    int lane = tid & 31;
    int wid  = tid >> 5;
    int wm   = wid & 3;          // warp m-index 0..3
    int wn   = wid >> 2;         // warp n-index 0..1
    int g    = lane >> 2;        // group 0..7
    int t    = lane & 3;         // thread-in-group 0..3

    int n0 = blockIdx.x * 64;    // o-tile base
    int m0 = blockIdx.y * BM;
    int b  = m0 >> 12;
    int l0 = m0 & (LEN - 1);

    // ---- loader assignment: row = tid&127, two k-slots each ----
    int lrow = tid & 127;
    int sh   = tid >> 7;          // 0..1
    int s0   = 2 * sh;            // slot base (s0, s0+1)
    int lswz = (lrow ^ (lrow >> 2)) & 3;
    int stA0 = lrow * 16 + (((s0)     ^ lswz) << 2);
    int stA1 = lrow * 16 + (((s0 + 1) ^ lswz) << 2);

    // base pointers with the runtime slot folded in; bumped by BK*stride per iter
    const float* A0 = g_Yg + (size_t)b * CHN * LEN + (size_t)s0 * LEN + l0 + lrow;
    const float* A1 = A0 + LEN;
    int og = (lrow & 1) ? (NH + n0 + (lrow >> 1)) : (n0 + (lrow >> 1));
    const float* B0 = g_Wr + (size_t)s0 * NOUT + og;
    const float* B1 = B0 + NOUT;

    // ---- fragment offsets (loop-invariant) ----
    int aoff[2][2], boff[8];
    #pragma unroll
    for (int mi = 0; mi < 2; mi++) {
        int r0 = wm * 32 + mi * 16 + g;
        int r1 = r0 + 8;
        aoff[mi][0] = r0 * 16 + ((t ^ ((r0 ^ (r0 >> 2)) & 3)) << 2);
        aoff[mi][1] = r1 * 16 + ((t ^ ((r1 ^ (r1 >> 2)) & 3)) << 2);
    }
    #pragma unroll
    for (int ni = 0; ni < 8; ni++) {
        int rb = wn * 64 + ni * 8 + g;
        boff[ni] = rb * 16 + ((t ^ ((rb ^ (rb >> 2)) & 3)) << 2);
    }

    float c[2][8][4];
    #pragma unroll
    for (int mi = 0; mi < 2; mi++)
        #pragma unroll
        for (int ni = 0; ni < 8; ni++)
            #pragma unroll
            for (int q = 0; q < 4; q++) c[mi][ni][q] = 0.f;

    float ar0[4], ar1[4], br0[4], br1[4];

    // constant-immediate-offset LDGs; pointers advance by BK*stride after use
    #define LDG_TILE()                                            \
    {                                                             \
        _Pragma("unroll")                                         \
        for (int e = 0; e < 4; e++) {                             \
            ar0[e] = A0[(size_t)(4*e) * LEN];                     \
            ar1[e] = A1[(size_t)(4*e) * LEN];                     \
            br0[e] = B0[(size_t)(4*e) * NOUT];                    \
            br1[e] = B1[(size_t)(4*e) * NOUT];                    \
        }                                                         \
        A0 += (size_t)BK * LEN;  A1 += (size_t)BK * LEN;          \
        B0 += (size_t)BK * NOUT; B1 += (size_t)BK * NOUT;         \
    }

    #define STS_TILE(buf)                                         \
    {                                                             \
        *(float4*)&As[buf][stA0] =                                \
            make_float4(ar0[0], ar0[1], ar0[2], ar0[3]);          \
        *(float4*)&As[buf][stA1] =                                \
            make_float4(ar1[0], ar1[1], ar1[2], ar1[3]);          \
        *(float4*)&Bs[buf][stA0] =                                \
            make_float4(br0[0], br0[1], br0[2], br0[3]);          \
        *(float4*)&Bs[buf][stA1] =                                \
            make_float4(br1[0], br1[1], br1[2], br1[3]);          \
    }

    LDG_TILE();
    STS_TILE(0);
    __syncthreads();

    #pragma unroll 1
    for (int it = 0; it < KITERS; it++) {
        int cur = it & 1;
        if (it + 1 < KITERS) LDG_TILE();

        const float* Ab = As[cur];
        const float* Bb = Bs[cur];
        uint4 va[2][2];
        #pragma unroll
        for (int mi = 0; mi < 2; mi++) {
            va[mi][0] = *(const uint4*)&Ab[aoff[mi][0]];
            va[mi][1] = *(const uint4*)&Ab[aoff[mi][1]];
        }
        #pragma unroll
        for (int ni = 0; ni < 8; ni++) {
            uint4 vb = *(const uint4*)&Bb[boff[ni]];
            #pragma unroll
            for (int mi = 0; mi < 2; mi++) {
                asm volatile(
                    "mma.sync.aligned.m16n8k8.row.col.f32.tf32.tf32.f32 "
                    "{%0,%1,%2,%3}, {%4,%5,%6,%7}, {%8,%9}, {%0,%1,%2,%3};"
                    : "+f"(c[mi][ni][0]), "+f"(c[mi][ni][1]),
                      "+f"(c[mi][ni][2]), "+f"(c[mi][ni][3])
                    : "r"(va[mi][0].x), "r"(va[mi][1].x),
                      "r"(va[mi][0].y), "r"(va[mi][1].y),
                      "r"(vb.x), "r"(vb.y));
                asm volatile(
                    "mma.sync.aligned.m16n8k8.row.col.f32.tf32.tf32.f32 "
                    "{%0,%1,%2,%3}, {%4,%5,%6,%7}, {%8,%9}, {%0,%1,%2,%3};"
                    : "+f"(c[mi][ni][0]), "+f"(c[mi][ni][1]),
                      "+f"(c[mi][ni][2]), "+f"(c[mi][ni][3])
                    : "r"(va[mi][0].z), "r"(va[mi][1].z),
                      "r"(va[mi][0].w), "r"(va[mi][1].w),
                      "r"(vb.z), "r"(vb.w));
            }
        }
        if (it + 1 < KITERS) STS_TILE(1 - cur);
        __syncthreads();
    }

    // ---- epilogue: GLU pairs in (c0,c1) and (c2,c3) ----
    #pragma unroll
    for (int ni = 0; ni < 8; ni++) {
        int o = n0 + wn * 32 + ni * 4 + t;
        float bb0 = bias[o];
        float bb1 = bias[o + NH];
        float* orow = out + ((size_t)b * NH + o) * LEN;
        #pragma unroll
        for (int mi = 0; mi < 2; mi++) {
            int l = l0 + wm * 32 + mi * 16 + g;
            float z1 = c[mi][ni][0] + bb0;
            float z2 = c[mi][ni][1] + bb1;
            orow[l] = z1 / (1.f + __expf(-z2));
            float z3 = c[mi][ni][2] + bb0;
            float z4 = c[mi][ni][3] + bb1;
            orow[l + 8] = z3 / (1.f + __expf(-z4));
        }
    }
}

// ------------------------- launch -------------------------
extern "C" void kernel_launch(void* const* d_in, const int* in_sizes, int n_in,
                              void* d_out, int out_size) {
    const float* u    = (const float*)d_in[0];
    const float* D    = (const float*)d_in[1];
    const float* kern = (const float*)d_in[2];
    const float* W    = (const float*)d_in[3];
    const float* bias = (const float*)d_in[4];
    float* out = (float*)d_out;

    int smemF = 2 * NFFT * sizeof(float2);   // 128 KB
    cudaFuncSetAttribute(kf2_kernel,  cudaFuncAttributeMaxDynamicSharedMemorySize, smemF);
    cudaFuncSetAttribute(uf2_kernel,  cudaFuncAttributeMaxDynamicSharedMemorySize, smemF);
    cudaFuncSetAttribute(conv_kernel, cudaFuncAttributeMaxDynamicSharedMemorySize, smemF);

    wround_kernel<<<CHN * NOUT / 256, 256>>>(W);
    kf2_kernel <<<CHN / 2,       1024, smemF>>>(kern);
    uf2_kernel <<<NB * NH / 2,   1024, smemF>>>(u);
    conv_kernel<<<NB * NH,       1024, smemF>>>(u, D);

    dim3 g(NH / 64, NB * LEN / BM);   // (12, 128)
    gemm_glu_mma<<<g, 256>>>(bias, out);
}